// round 16
// baseline (speedup 1.0000x reference)
#include <cuda_runtime.h>
#include <math.h>

// AMPS fast log-prob, v12: R6 proven main + shfl-free pipelined combine/reduce tail.
//   chain(n, bs): v = e0^T * Prod_{m=0..n} A(n,m,bs);  A = plane-selected 4x4 of tri_up[n(n+1)/2+m]
//   logits[n+1][bs][p] = v . diag[n+1][:,p];  out[bs] = sum_n logsoftmax(logits[n])[sel]
// Main: work unit = 64-step 4x4 chunk product (m in [64c, 64c+63]), lane = (chunk g, sample bs),
//       full P[16] in regs, A distributed via warp-private smem tiles (no shfl).
// Combine: thread per (n, bs); v in regs; chunk matrices double-buffered via LDG.128;
//          fused log-softmax; last block reduces (atomic counter, deterministic order).

#define NN    1024
#define NCH   1023
#define SMCH  64
#define FULLM 0xffffffffu
#define TT    8
#define NCID  8688
#define NBLK  272     // ceil(8688/4/8)

__device__ float g_M[NCID * 128];         // [cid][bs*16 + i*4 + j]
__device__ float g_contrib[8 * 1024];     // [bs][out position]
__device__ int g_count;

__constant__ int c_off[17] = {0,1023,1982,2877,3708,4475,5178,5817,6392,6903,
                              7350,7733,8052,8307,8498,8625,8688};

__global__ __launch_bounds__(256, 2) void amps_main(const float* __restrict__ data,
                                                    const float* __restrict__ tri) {
    __shared__ unsigned ssel[NN];
    __shared__ float4 sm[8 * 264];   // per warp: 4 groups * 66 float4 (8 steps * 8 slots + skew)

    const int tid = threadIdx.x, warp = tid >> 5, lane = tid & 31;
    const int g = lane >> 3, bs = lane & 7;

    if (blockIdx.x == 0 && tid == 0) g_count = 0;   // reset for combine (kernel-order visible)

    // block-local selector bits: bit bs of ssel[m] = plane (0 if data!=0 else 1)
    for (int m = tid; m < NN; m += 256) {
        unsigned s = 0;
#pragma unroll
        for (int b = 0; b < 8; b++) s |= ((data[b * NN + m] != 0.0f) ? 0u : 1u) << b;
        ssel[m] = s;
    }
    __syncthreads();

    float4* smw = sm + warp * 264 + g * 66;
    const float4* tri4 = (const float4*)tri;

    const int cid = (blockIdx.x * 8 + warp) * 4 + g;
    const bool valid = (cid < NCID);
    const int cc = valid ? cid : 0;
    int c = 0;
#pragma unroll
    for (int j = 1; j < 16; j++) if (cc >= c_off[j]) c = j;
    const int n = 64 * c + (cc - c_off[c]);
    const int mS = 64 * c;
    const int mE = min(n, mS + SMCH - 1);
    const int steps = mE - mS + 1;
    const int ws = __reduce_max_sync(FULLM, steps);
    const size_t t0 = (size_t)n * (n + 1) / 2;
    const float4* base = tri4 + (t0 + mS) * 8;
    const int sc = steps - 1;

    float P[16];
#pragma unroll
    for (int q = 0; q < 16; q++) P[q] = (q % 5 == 0) ? 1.0f : 0.0f;

    float4 r[TT];
#pragma unroll
    for (int t = 0; t < TT; t++) r[t] = __ldg(base + (size_t)min(t, sc) * 8 + bs);

    for (int st = 0; st < ws; st += TT) {
        __syncwarp();
#pragma unroll
        for (int t = 0; t < TT; t++) smw[t * 8 + bs] = r[t];
        __syncwarp();
        if (st + TT < ws) {
#pragma unroll
            for (int t = 0; t < TT; t++)
                r[t] = __ldg(base + (size_t)min(st + TT + t, sc) * 8 + bs);
        }
#pragma unroll
        for (int t = 0; t < TT; t++) {
            const int s = st + t;
            const unsigned sw = ssel[mS + s <= (NN - 1) ? mS + s : (NN - 1)];
            const bool p = (sw >> bs) & 1u;
            float a[16];
#pragma unroll
            for (int q = 0; q < 8; q++) {
                float4 w = smw[t * 8 + q];
                a[(q >> 1) * 4 + (q & 1) * 2]     = p ? w.y : w.x;
                a[(q >> 1) * 4 + (q & 1) * 2 + 1] = p ? w.w : w.z;
            }
            if (s < steps) {
#pragma unroll
                for (int i = 0; i < 4; i++) {
                    float q0 = P[i*4+0]*a[0] + P[i*4+1]*a[4] + P[i*4+2]*a[8]  + P[i*4+3]*a[12];
                    float q1 = P[i*4+0]*a[1] + P[i*4+1]*a[5] + P[i*4+2]*a[9]  + P[i*4+3]*a[13];
                    float q2 = P[i*4+0]*a[2] + P[i*4+1]*a[6] + P[i*4+2]*a[10] + P[i*4+3]*a[14];
                    float q3 = P[i*4+0]*a[3] + P[i*4+1]*a[7] + P[i*4+2]*a[11] + P[i*4+3]*a[15];
                    P[i*4+0] = q0; P[i*4+1] = q1; P[i*4+2] = q2; P[i*4+3] = q3;
                }
            }
        }
    }
    if (valid) {
        float4* dst = (float4*)&g_M[(size_t)cid * 128 + bs * 16];
#pragma unroll
        for (int i = 0; i < 4; i++)
            dst[i] = make_float4(P[i*4], P[i*4+1], P[i*4+2], P[i*4+3]);
    }
}

// ---------------- combine: thread per (n,bs); pipelined chunk chain; lse; last-block reduce ----------------
__global__ __launch_bounds__(256) void amps_combine(const float* __restrict__ data,
                                                    const float* __restrict__ diag,
                                                    float* __restrict__ out) {
    const int tid0 = blockIdx.x * 256 + threadIdx.x;
    const int n = tid0 >> 3, bs = tid0 & 7;

    if (n < NCH) {
        // v = row 0 of chunk 0 (cid = n)
        float4 v = *(const float4*)&g_M[(size_t)n * 128 + bs * 16];
        const int nch = (n >> 6) + 1;

        float4 m0, m1, m2, m3;
        if (nch > 1) {
            const float4* Mb = (const float4*)&g_M[(size_t)(c_off[1] + n - 64) * 128 + bs * 16];
            m0 = __ldg(Mb); m1 = __ldg(Mb + 1); m2 = __ldg(Mb + 2); m3 = __ldg(Mb + 3);
        }
        for (int c = 1; c < nch; c++) {
            float4 a0 = m0, a1 = m1, a2 = m2, a3 = m3;
            if (c + 1 < nch) {
                const float4* Mb = (const float4*)&g_M[(size_t)(c_off[c + 1] + n - 64 * (c + 1)) * 128 + bs * 16];
                m0 = __ldg(Mb); m1 = __ldg(Mb + 1); m2 = __ldg(Mb + 2); m3 = __ldg(Mb + 3);
            }
            float4 nv;
            nv.x = v.x * a0.x + v.y * a1.x + v.z * a2.x + v.w * a3.x;
            nv.y = v.x * a0.y + v.y * a1.y + v.z * a2.y + v.w * a3.y;
            nv.z = v.x * a0.z + v.y * a1.z + v.z * a2.z + v.w * a3.z;
            nv.w = v.x * a0.w + v.y * a1.w + v.z * a2.w + v.w * a3.w;
            v = nv;
        }
        const float4* dg4 = (const float4*)(diag + (size_t)(n + 1) * 8);
        float4 d0 = __ldg(dg4), d1 = __ldg(dg4 + 1);
        float x0 = v.x * d0.x + v.y * d0.z + v.z * d1.x + v.w * d1.z;
        float x1 = v.x * d0.y + v.y * d0.w + v.z * d1.y + v.w * d1.w;
        float mx = fmaxf(x0, x1);
        float lse = mx + log1pf(expf(-fabsf(x0 - x1)));
        bool p1 = (data[bs * NN + (n + 1)] == 0.0f);
        g_contrib[bs * 1024 + n + 1] = (p1 ? x1 : x0) - lse;
    }

    // ---- last block reduces everything (deterministic order) ----
    __shared__ int sdone;
    __threadfence();
    __syncthreads();
    if (threadIdx.x == 0) sdone = (atomicAdd(&g_count, 1) == gridDim.x - 1) ? 1 : 0;
    __syncthreads();
    if (!sdone) return;
    __threadfence();

    const int rbs = threadIdx.x >> 5;   // warp = sample
    const int rl = threadIdx.x & 31;
    float acc = 0.0f;
    const float4* cb = (const float4*)(g_contrib + rbs * 1024);
#pragma unroll
    for (int it = 0; it < 8; it++) {
        float4 v = cb[it * 32 + rl];
        if (it == 0 && rl == 0) {
            float x0 = diag[0], x1 = diag[1];
            float mx = fmaxf(x0, x1);
            float lse = mx + log1pf(expf(-fabsf(x0 - x1)));
            v.x = ((data[rbs * NN] == 0.0f) ? x1 : x0) - lse;  // n=0 term
        }
        acc += v.x + v.y + v.z + v.w;
    }
#pragma unroll
    for (int o = 16; o; o >>= 1) acc += __shfl_xor_sync(FULLM, acc, o);
    if (rl == 0) out[rbs] = acc;
}

extern "C" void kernel_launch(void* const* d_in, const int* in_sizes, int n_in,
                              void* d_out, int out_size) {
    const float* data = (const float*)d_in[0];
    const float* tri  = (const float*)d_in[1];
    const float* diag = (const float*)d_in[2];
    float* out = (float*)d_out;

    amps_main<<<NBLK, 256>>>(data, tri);
    amps_combine<<<32, 256>>>(data, diag, out);
}